// round 6
// baseline (speedup 1.0000x reference)
#include <cuda_runtime.h>

// Per-edge dot product: out[e] = dot(h[src[e]], h[dst[e]]), D=64 fp32.
// NOTE: JAX default config downcasts int64 -> int32, so indices arrive as int32.
// 8 threads per edge; each thread handles 8 floats (2x float4) of each row.
// Rows are 256B -> 8 lanes x 16B x 2 covers both 128B lines fully coalesced.
__global__ void __launch_bounds__(256) edge_dot_kernel(
    const float4* __restrict__ h,     // [N, 16] as float4 (D=64)
    const int* __restrict__ src,      // [E] int32
    const int* __restrict__ dst,      // [E] int32
    float* __restrict__ out,          // [E]
    int E)
{
    int tid  = blockIdx.x * blockDim.x + threadIdx.x;
    int e    = tid >> 3;   // 8 threads per edge
    int lane = tid & 7;
    if (e >= E) return;

    int s = __ldg(src + e);
    int d = __ldg(dst + e);
    const float4* __restrict__ hu = h + (long long)s * 16;
    const float4* __restrict__ hv = h + (long long)d * 16;

    // 4 independent 16B loads -> MLP
    float4 a0 = hu[lane];
    float4 a1 = hu[lane + 8];
    float4 b0 = hv[lane];
    float4 b1 = hv[lane + 8];

    float p = a0.x * b0.x + a0.y * b0.y + a0.z * b0.z + a0.w * b0.w
            + a1.x * b1.x + a1.y * b1.y + a1.z * b1.z + a1.w * b1.w;

    // Butterfly reduce across the 8-lane group
    p += __shfl_xor_sync(0xFFFFFFFFu, p, 4);
    p += __shfl_xor_sync(0xFFFFFFFFu, p, 2);
    p += __shfl_xor_sync(0xFFFFFFFFu, p, 1);

    if (lane == 0) out[e] = p;
}

extern "C" void kernel_launch(void* const* d_in, const int* in_sizes, int n_in,
                              void* d_out, int out_size)
{
    const float4* h   = (const float4*)d_in[0];   // [N*64] fp32 viewed as float4
    const int*    src = (const int*)d_in[1];      // int32 (JAX x64 disabled)
    const int*    dst = (const int*)d_in[2];      // int32
    float*        out = (float*)d_out;

    int E = in_sizes[1];  // number of edges

    int threads = 256;
    long long total = (long long)E * 8;           // 8 threads per edge
    int blocks = (int)((total + threads - 1) / threads);
    edge_dot_kernel<<<blocks, threads>>>(h, src, dst, out, E);
}

// round 7
// speedup vs baseline: 1.0632x; 1.0632x over previous
#include <cuda_runtime.h>

// Per-edge dot product: out[e] = dot(h[src[e]], h[dst[e]]), D=64 fp32.
// Indices arrive as int32 (JAX x64 disabled).
//
// R6 profile showed nothing saturated (L2 58%, L1 52%, issue 30%) -> latency
// bound with only 4 outstanding LDG.128/thread. This version processes TWO
// edges per 8-lane group: 8 independent LDG.128 per thread in flight before
// any FMA consumes them, doubling MLP at ~2x register cost (still >=50% occ).
__global__ void __launch_bounds__(256) edge_dot_kernel(
    const float4* __restrict__ h,     // [N, 16] as float4 (D=64)
    const int* __restrict__ src,      // [E] int32
    const int* __restrict__ dst,      // [E] int32
    float* __restrict__ out,          // [E]
    int E)
{
    int tid   = blockIdx.x * blockDim.x + threadIdx.x;
    int group = tid >> 3;             // 8 lanes per group, 2 edges per group
    int lane  = tid & 7;

    int e0 = group * 2;
    int e1 = e0 + 1;
    if (e0 >= E) return;
    bool has1 = (e1 < E);

    // Load all indices up front (broadcast within warp; L1-resident)
    int s0 = __ldg(src + e0);
    int d0 = __ldg(dst + e0);
    int s1 = has1 ? __ldg(src + e1) : s0;
    int d1 = has1 ? __ldg(dst + e1) : d0;

    const float4* __restrict__ hu0 = h + (long long)s0 * 16;
    const float4* __restrict__ hv0 = h + (long long)d0 * 16;
    const float4* __restrict__ hu1 = h + (long long)s1 * 16;
    const float4* __restrict__ hv1 = h + (long long)d1 * 16;

    // 8 independent 16B loads -> deep MLP, both 128B lines of each 256B row
    // fully coalesced across the 8-lane group.
    float4 a00 = hu0[lane];
    float4 a01 = hu0[lane + 8];
    float4 b00 = hv0[lane];
    float4 b01 = hv0[lane + 8];
    float4 a10 = hu1[lane];
    float4 a11 = hu1[lane + 8];
    float4 b10 = hv1[lane];
    float4 b11 = hv1[lane + 8];

    float p0 = a00.x * b00.x + a00.y * b00.y + a00.z * b00.z + a00.w * b00.w
             + a01.x * b01.x + a01.y * b01.y + a01.z * b01.z + a01.w * b01.w;
    float p1 = a10.x * b10.x + a10.y * b10.y + a10.z * b10.z + a10.w * b10.w
             + a11.x * b11.x + a11.y * b11.y + a11.z * b11.z + a11.w * b11.w;

    // Butterfly reduce both edges across the 8-lane group
    p0 += __shfl_xor_sync(0xFFFFFFFFu, p0, 4);
    p1 += __shfl_xor_sync(0xFFFFFFFFu, p1, 4);
    p0 += __shfl_xor_sync(0xFFFFFFFFu, p0, 2);
    p1 += __shfl_xor_sync(0xFFFFFFFFu, p1, 2);
    p0 += __shfl_xor_sync(0xFFFFFFFFu, p0, 1);
    p1 += __shfl_xor_sync(0xFFFFFFFFu, p1, 1);

    if (lane == 0) {
        out[e0] = p0;
        if (has1) out[e1] = p1;
    }
}

extern "C" void kernel_launch(void* const* d_in, const int* in_sizes, int n_in,
                              void* d_out, int out_size)
{
    const float4* h   = (const float4*)d_in[0];
    const int*    src = (const int*)d_in[1];
    const int*    dst = (const int*)d_in[2];
    float*        out = (float*)d_out;

    int E = in_sizes[1];

    int threads = 256;
    long long groups = ((long long)E + 1) / 2;      // 2 edges per group
    long long total  = groups * 8;                  // 8 lanes per group
    int blocks = (int)((total + threads - 1) / threads);
    edge_dot_kernel<<<blocks, threads>>>(h, src, dst, out, E);
}